// round 9
// baseline (speedup 1.0000x reference)
#include <cuda_runtime.h>

#define FULLMASK 0xffffffffu
typedef unsigned long long ull;

// ---------- packed f32x2 helpers (Blackwell sm_103a) ----------
__device__ __forceinline__ ull pk2(float a, float b) {
    ull r;
    asm("mov.b64 %0, {%1, %2};" : "=l"(r) : "f"(a), "f"(b));
    return r;
}
__device__ __forceinline__ float2 upk2(ull v) {
    float2 r;
    asm("mov.b64 {%0, %1}, %2;" : "=f"(r.x), "=f"(r.y) : "l"(v));
    return r;
}
__device__ __forceinline__ ull dup2(float a) { return pk2(a, a); }

__device__ __forceinline__ ull ffma2(ull a, ull b, ull c) {
    ull d;
    asm("fma.rn.f32x2 %0, %1, %2, %3;" : "=l"(d) : "l"(a), "l"(b), "l"(c));
    return d;
}
__device__ __forceinline__ ull add2(ull a, ull b) {
    ull d;
    asm("add.rn.f32x2 %0, %1, %2;" : "=l"(d) : "l"(a), "l"(b));
    return d;
}

// tanh with PRE-SCALED argument: zs = 2*log2(e)*z folded into weights.
// tanh(z) = 1 - 2/(exp2(zs)+1)   (abs err ~1e-7)
__device__ __forceinline__ float tanh_pre(float zs) {
    float e;
    asm("ex2.approx.f32 %0, %1;" : "=f"(e) : "f"(zs));
    float r;
    asm("rcp.approx.f32 %0, %1;" : "=f"(r) : "f"(e + 1.0f));
    return fmaf(-2.0f, r, 1.0f);
}

// FOUR batch elements per 32-lane warp (ILP 4), R4 layout:
// lane l owns h1 units (2l,2l+1) and layer-2 cols (l, l+32); W2 in 128 regs
// shared across all 4 elements. Exchange: STS.64 + broadcast LDS.128.
// Next-step eps-partial of layer 1 + x prefetch are hoisted between the FMA
// blocks and the two interleaved packed butterflies to fill SHFL stalls.
__global__ void __launch_bounds__(32)
maxwell_ffnn_kernel(const float* __restrict__ x,
                    const float* __restrict__ W1,
                    const float* __restrict__ b1,
                    const float* __restrict__ W2,
                    const float* __restrict__ b2,
                    const float* __restrict__ W3,
                    const float* __restrict__ b3,
                    float* __restrict__ out) {
    __shared__ __align__(16) ull hbuf[2][4][32];   // [parity][elem][lane]

    const int l  = threadIdx.x & 31;
    const int jA = l;
    const int jB = l + 32;
    const int u0 = 2 * l;

    const float Kf = 2.8853900817779268f;   // 2*log2(e), folded into pre-activations

    // ---- loop-invariant weights in registers (pre-scaled by Kf) ----
    const ull c1a = pk2(Kf * __ldg(&W1[u0]),      Kf * __ldg(&W1[u0 + 1]));
    const ull c1b = pk2(Kf * __ldg(&W1[64 + u0]), Kf * __ldg(&W1[64 + u0 + 1]));
    const ull cb1 = pk2(Kf * __ldg(&b1[u0]),      Kf * __ldg(&b1[u0 + 1]));

    ull w2A[32], w2B[32];
#pragma unroll
    for (int s = 0; s < 32; ++s) {
        w2A[s] = pk2(Kf * __ldg(&W2[(2 * s) * 64 + jA]),
                     Kf * __ldg(&W2[(2 * s + 1) * 64 + jA]));
        w2B[s] = pk2(Kf * __ldg(&W2[(2 * s) * 64 + jB]),
                     Kf * __ldg(&W2[(2 * s + 1) * 64 + jB]));
    }
    const float b2A = Kf * __ldg(&b2[jA]);
    const float b2B = Kf * __ldg(&b2[jB]);
    const float w3A = __ldg(&W3[jA]);
    const float w3B = __ldg(&W3[jB]);
    const float b3v = __ldg(&b3[0]);

    // contiguous 4-element group: single base pointers, immediate offsets
    const float2* xb = (const float2*)(x + (size_t)(blockIdx.x * 4) * 2048);
    float*        ob = out + (size_t)(blockIdx.x * 4) * 1024;

    float g[4]   = {0.0f, 0.0f, 0.0f, 0.0f};
    float eps[4], dtn[4];
    ull   pre[4];                       // eps-part of layer-1 pre-activation
#pragma unroll
    for (int e = 0; e < 4; ++e) {
        const float2 v = __ldg(&xb[e * 1024]);
        eps[e] = v.x;
        dtn[e] = v.y;
        pre[e] = ffma2(dup2(eps[e]), c1a, cb1);
    }
    const ull zero2 = pk2(0.0f, 0.0f);

#pragma unroll 2
    for (int t = 0; t < 1024; ++t) {
        const int par = t & 1;

        // ---- layer 1 finish (gamma-dependent) + publish, all 4 elements ----
#pragma unroll
        for (int e = 0; e < 4; ++e) {
            const ull z = ffma2(dup2(g[e]), c1b, pre[e]);
            const float2 q = upk2(z);
            hbuf[par][e][l] = pk2(tanh_pre(q.x), tanh_pre(q.y));
        }
        __syncwarp();

        // ---- layer 2 + 3 partial, all 4 elements (4 chains each) ----
        float gp[4];
#pragma unroll
        for (int e = 0; e < 4; ++e) {
            const ulonglong2* hp = (const ulonglong2*)&hbuf[par][e][0];
            ull A0 = pk2(b2A, 0.0f), A1 = zero2;
            ull B0 = pk2(b2B, 0.0f), B1 = zero2;
#pragma unroll
            for (int k = 0; k < 16; ++k) {
                const ulonglong2 hh = hp[k];
                A0 = ffma2(hh.x, w2A[2 * k],     A0);
                B0 = ffma2(hh.x, w2B[2 * k],     B0);
                A1 = ffma2(hh.y, w2A[2 * k + 1], A1);
                B1 = ffma2(hh.y, w2B[2 * k + 1], B1);
            }
            const float2 aA = upk2(add2(A0, A1));
            const float2 aB = upk2(add2(B0, B1));
            gp[e] = fmaf(tanh_pre(aA.x + aA.y), w3A,
                         tanh_pre(aB.x + aB.y) * w3B);
        }

        // ---- off-chain work hoisted to overlap the butterflies ----
        float gq[4];                       // gamma + dtn*b3
#pragma unroll
        for (int e = 0; e < 4; ++e) gq[e] = fmaf(dtn[e], b3v, g[e]);

        float neps[4], ndtn[4];
        if (t < 1023) {
#pragma unroll
            for (int e = 0; e < 4; ++e) {
                const float2 v = __ldg(&xb[e * 1024 + t + 1]);
                neps[e] = v.x;
                ndtn[e] = v.y;
                pre[e]  = ffma2(dup2(neps[e]), c1a, cb1);   // next-step eps part
            }
        }

        // ---- two packed butterflies, interleaved (latencies overlap) ----
        ull g01 = pk2(gp[0], gp[1]);
        ull g23 = pk2(gp[2], gp[3]);
#pragma unroll
        for (int d = 1; d < 32; d <<= 1) {
            const ull s01 = __shfl_xor_sync(FULLMASK, g01, d);
            const ull s23 = __shfl_xor_sync(FULLMASK, g23, d);
            g01 = add2(g01, s01);
            g23 = add2(g23, s23);
        }
        const float2 s01 = upk2(g01);
        const float2 s23 = upk2(g23);

        // ---- gamma updates + outputs (sigma = 2.5*eps - 2*gamma) ----
        g[0] = fmaf(dtn[0], s01.x, gq[0]);
        g[1] = fmaf(dtn[1], s01.y, gq[1]);
        g[2] = fmaf(dtn[2], s23.x, gq[2]);
        g[3] = fmaf(dtn[3], s23.y, gq[3]);

        if (l == 0) ob[t]        = fmaf(-2.0f, g[0], 2.5f * eps[0]);
        if (l == 1) ob[1024 + t] = fmaf(-2.0f, g[1], 2.5f * eps[1]);
        if (l == 2) ob[2048 + t] = fmaf(-2.0f, g[2], 2.5f * eps[2]);
        if (l == 3) ob[3072 + t] = fmaf(-2.0f, g[3], 2.5f * eps[3]);

#pragma unroll
        for (int e = 0; e < 4; ++e) { eps[e] = neps[e]; dtn[e] = ndtn[e]; }
    }
}

extern "C" void kernel_launch(void* const* d_in, const int* in_sizes, int n_in,
                              void* d_out, int out_size) {
    (void)in_sizes; (void)n_in; (void)out_size;
    const float* x  = (const float*)d_in[0];
    const float* W1 = (const float*)d_in[1];
    const float* b1 = (const float*)d_in[2];
    const float* W2 = (const float*)d_in[3];
    const float* b2 = (const float*)d_in[4];
    const float* W3 = (const float*)d_in[5];
    const float* b3 = (const float*)d_in[6];
    float* out = (float*)d_out;

    // 4 elements per warp: 512 single-warp CTAs (3.46/SM)
    maxwell_ffnn_kernel<<<512, 32>>>(x, W1, b1, W2, b2, W3, b3, out);
}

// round 10
// speedup vs baseline: 1.2676x; 1.2676x over previous
#include <cuda_runtime.h>

#define FULLMASK 0xffffffffu
typedef unsigned long long ull;

// ---------- packed f32x2 helpers (Blackwell sm_103a) ----------
__device__ __forceinline__ ull pk2(float a, float b) {
    ull r;
    asm("mov.b64 %0, {%1, %2};" : "=l"(r) : "f"(a), "f"(b));
    return r;
}
__device__ __forceinline__ float2 upk2(ull v) {
    float2 r;
    asm("mov.b64 {%0, %1}, %2;" : "=f"(r.x), "=f"(r.y) : "l"(v));
    return r;
}
__device__ __forceinline__ ull dup2(float a) { return pk2(a, a); }

__device__ __forceinline__ ull ffma2(ull a, ull b, ull c) {
    ull d;
    asm("fma.rn.f32x2 %0, %1, %2, %3;" : "=l"(d) : "l"(a), "l"(b), "l"(c));
    return d;
}
__device__ __forceinline__ ull add2(ull a, ull b) {
    ull d;
    asm("add.rn.f32x2 %0, %1, %2;" : "=l"(d) : "l"(a), "l"(b));
    return d;
}

// tanh with PRE-SCALED argument: zs = 2*log2(e)*z folded into weights.
// tanh(z) = 1 - 2/(exp2(zs)+1)   (abs err ~1e-7)
__device__ __forceinline__ float tanh_pre(float zs) {
    float e;
    asm("ex2.approx.f32 %0, %1;" : "=f"(e) : "f"(zs));
    float r;
    asm("rcp.approx.f32 %0, %1;" : "=f"(r) : "f"(e + 1.0f));
    return fmaf(-2.0f, r, 1.0f);
}

// warp-wide integer sum (sm_80+; fp32 redux is NOT on sm_103)
__device__ __forceinline__ float redux_scaled(float gp_scaled) {
    int gi, si;
    asm("cvt.rni.s32.f32 %0, %1;" : "=r"(gi) : "f"(gp_scaled));
    asm("redux.sync.add.s32 %0, %1, 0xffffffff;" : "=r"(si) : "r"(gi));
    float sf;
    asm("cvt.rn.f32.s32 %0, %1;" : "=f"(sf) : "r"(si));
    return sf;   // = round-sum of gp*2^23 values
}

// TWO elements per warp, SOFTWARE-PIPELINED half a step apart:
//  region A: layer1+publish e0(t)      || layer2+reduce+gamma e1(t)
//  region B: layer1+publish e1(t+1)    || layer2+reduce+gamma e0(t)
// so each element's FMA block overlaps the sibling's tanh/exchange/reduce tail
// INSIDE the warp. Reduction via redux.sync.add.s32 (W3 pre-scaled by 2^23).
__global__ void __launch_bounds__(32)
maxwell_ffnn_kernel(const float* __restrict__ x,
                    const float* __restrict__ W1,
                    const float* __restrict__ b1,
                    const float* __restrict__ W2,
                    const float* __restrict__ b2,
                    const float* __restrict__ W3,
                    const float* __restrict__ b3,
                    float* __restrict__ out) {
    __shared__ __align__(16) ull h0buf[32];
    __shared__ __align__(16) ull h1buf[2][32];   // parity-buffered (WAR safety)

    const int l  = threadIdx.x & 31;
    const int jA = l;
    const int jB = l + 32;
    const int u0 = 2 * l;

    const float Kf = 2.8853900817779268f;        // 2*log2(e)
    const float IS = 1.1920928955078125e-7f;     // 2^-23

    // ---- loop-invariant weights (layer1/2 pre-scaled by Kf; W3 by 2^23) ----
    const ull c1a = pk2(Kf * __ldg(&W1[u0]),      Kf * __ldg(&W1[u0 + 1]));
    const ull c1b = pk2(Kf * __ldg(&W1[64 + u0]), Kf * __ldg(&W1[64 + u0 + 1]));
    const ull cb1 = pk2(Kf * __ldg(&b1[u0]),      Kf * __ldg(&b1[u0 + 1]));

    ull w2A[32], w2B[32];
#pragma unroll
    for (int s = 0; s < 32; ++s) {
        w2A[s] = pk2(Kf * __ldg(&W2[(2 * s) * 64 + jA]),
                     Kf * __ldg(&W2[(2 * s + 1) * 64 + jA]));
        w2B[s] = pk2(Kf * __ldg(&W2[(2 * s) * 64 + jB]),
                     Kf * __ldg(&W2[(2 * s + 1) * 64 + jB]));
    }
    const float b2A = Kf * __ldg(&b2[jA]);
    const float b2B = Kf * __ldg(&b2[jB]);
    const float w3A = 8388608.0f * __ldg(&W3[jA]);   // 2^23 * W3
    const float w3B = 8388608.0f * __ldg(&W3[jB]);
    const float b3v = __ldg(&b3[0]);

    const float2* xp0 = (const float2*)(x + (size_t)(blockIdx.x * 2) * 2048);
    const float2* xp1 = xp0 + 1024;
    float* op0 = out + (size_t)(blockIdx.x * 2) * 1024;
    float* op1 = op0 + 1024;

    const ull zero2 = pk2(0.0f, 0.0f);

    // layer-2 + layer-3 partial for one element; returns 2^23-scaled gp
    auto matvec = [&](const ull* hb) -> float {
        const ulonglong2* hp = (const ulonglong2*)hb;
        ull A0 = pk2(b2A, 0.0f), A1 = zero2, A2 = zero2, A3 = zero2;
        ull B0 = pk2(b2B, 0.0f), B1 = zero2, B2 = zero2, B3 = zero2;
#pragma unroll
        for (int k = 0; k < 8; ++k) {
            const ulonglong2 ha = hp[2 * k];
            const ulonglong2 hb2 = hp[2 * k + 1];
            A0 = ffma2(ha.x,  w2A[4 * k],     A0);
            B0 = ffma2(ha.x,  w2B[4 * k],     B0);
            A1 = ffma2(ha.y,  w2A[4 * k + 1], A1);
            B1 = ffma2(ha.y,  w2B[4 * k + 1], B1);
            A2 = ffma2(hb2.x, w2A[4 * k + 2], A2);
            B2 = ffma2(hb2.x, w2B[4 * k + 2], B2);
            A3 = ffma2(hb2.y, w2A[4 * k + 3], A3);
            B3 = ffma2(hb2.y, w2B[4 * k + 3], B3);
        }
        const float2 aA = upk2(add2(add2(A0, A1), add2(A2, A3)));
        const float2 aB = upk2(add2(add2(B0, B1), add2(B2, B3)));
        return fmaf(tanh_pre(aA.x + aA.y), w3A,
                    tanh_pre(aB.x + aB.y) * w3B);
    };

    float gamma0 = 0.0f, gamma1 = 0.0f;
    float2 xv0 = __ldg(&xp0[0]);
    float2 xv1 = __ldg(&xp1[0]);

    // ---- prologue: layer1 e1 (update 0, gamma1 = 0) ----
    {
        const ull z = ffma2(dup2(xv1.x), c1a, cb1);
        const float2 q = upk2(z);
        h1buf[0][l] = pk2(tanh_pre(q.x), tanh_pre(q.y));
    }
    __syncwarp();

#pragma unroll 1
    for (int t = 0; t < 1024; ++t) {
        const int par = t & 1;
        const float eps0 = xv0.x, dtn0 = xv0.y;
        const float eps1 = xv1.x, dtn1 = xv1.y;

        // ================= region A =================
        // layer1 e0 (update t)
        {
            const ull z = ffma2(dup2(gamma0), c1b, ffma2(dup2(eps0), c1a, cb1));
            const float2 q = upk2(z);
            h0buf[l] = pk2(tanh_pre(q.x), tanh_pre(q.y));
        }
        if (t < 1023) xv0 = __ldg(&xp0[t + 1]);     // prefetch e0

        // layer2 + reduce + gamma e1 (update t)
        {
            const float gp = matvec(&h1buf[par][0]);
            const float sf = redux_scaled(gp);
            const float gq = fmaf(dtn1, b3v, gamma1);        // off-chain
            gamma1 = fmaf(dtn1 * IS, sf, gq);
        }
        if (l == 1) op1[t] = fmaf(-2.0f, gamma1, 2.5f * eps1);
        __syncwarp();

        // ================= region B =================
        if (t < 1023) xv1 = __ldg(&xp1[t + 1]);     // prefetch e1 (next step)

        // layer1 e1 (update t+1) — uses freshly updated gamma1 and next eps1
        {
            const ull z = ffma2(dup2(gamma1), c1b, ffma2(dup2(xv1.x), c1a, cb1));
            const float2 q = upk2(z);
            h1buf[par ^ 1][l] = pk2(tanh_pre(q.x), tanh_pre(q.y));
        }

        // layer2 + reduce + gamma e0 (update t)
        {
            const float gp = matvec(&h0buf[0]);
            const float sf = redux_scaled(gp);
            const float gq = fmaf(dtn0, b3v, gamma0);        // off-chain
            gamma0 = fmaf(dtn0 * IS, sf, gq);
        }
        if (l == 0) op0[t] = fmaf(-2.0f, gamma0, 2.5f * eps0);
        __syncwarp();
    }
}

extern "C" void kernel_launch(void* const* d_in, const int* in_sizes, int n_in,
                              void* d_out, int out_size) {
    (void)in_sizes; (void)n_in; (void)out_size;
    const float* x  = (const float*)d_in[0];
    const float* W1 = (const float*)d_in[1];
    const float* b1 = (const float*)d_in[2];
    const float* W2 = (const float*)d_in[3];
    const float* b2 = (const float*)d_in[4];
    const float* W3 = (const float*)d_in[5];
    const float* b3 = (const float*)d_in[6];
    float* out = (float*)d_out;

    // 2 elements per warp, pipelined: 1024 single-warp CTAs (~7/SM, one wave)
    maxwell_ffnn_kernel<<<1024, 32>>>(x, W1, b1, W2, b2, W3, b3, out);
}

// round 11
// speedup vs baseline: 1.2762x; 1.0068x over previous
#include <cuda_runtime.h>

#define FULLMASK 0xffffffffu
typedef unsigned long long ull;

// ---------- packed f32x2 helpers (Blackwell sm_103a) ----------
__device__ __forceinline__ ull pk2(float a, float b) {
    ull r;
    asm("mov.b64 %0, {%1, %2};" : "=l"(r) : "f"(a), "f"(b));
    return r;
}
__device__ __forceinline__ float2 upk2(ull v) {
    float2 r;
    asm("mov.b64 {%0, %1}, %2;" : "=f"(r.x), "=f"(r.y) : "l"(v));
    return r;
}
__device__ __forceinline__ ull dup2(float a) { return pk2(a, a); }

__device__ __forceinline__ ull ffma2(ull a, ull b, ull c) {
    ull d;
    asm("fma.rn.f32x2 %0, %1, %2, %3;" : "=l"(d) : "l"(a), "l"(b), "l"(c));
    return d;
}
__device__ __forceinline__ ull add2(ull a, ull b) {
    ull d;
    asm("add.rn.f32x2 %0, %1, %2;" : "=l"(d) : "l"(a), "l"(b));
    return d;
}

// tanh with PRE-SCALED argument: zs = 2*log2(e)*z folded into weights.
// tanh(z) = 1 - 2/(exp2(zs)+1)   (abs err ~1e-7)
__device__ __forceinline__ float tanh_pre(float zs) {
    float e;
    asm("ex2.approx.f32 %0, %1;" : "=f"(e) : "f"(zs));
    float r;
    asm("rcp.approx.f32 %0, %1;" : "=f"(r) : "f"(e + 1.0f));
    return fmaf(-2.0f, r, 1.0f);
}

// 128-thread CTA = 4 INDEPENDENT warps (wid 0..3 -> all four SMSPs).
// Each warp privately runs the best-known 2-element pipeline (R4/R8):
//   lane l owns h1 units (2l,2l+1) and layer-2 cols (l, l+32);
//   W2 in 128 packed regs; exchange via private hbuf slice + __syncwarp;
//   depth-8 accumulator chains; interleaved scalar butterflies;
//   pre-scaled tanh; dtn*b3 folded off-chain.
// No __syncthreads anywhere in the loop — warps never interact.
__global__ void __launch_bounds__(128)
maxwell_ffnn_kernel(const float* __restrict__ x,
                    const float* __restrict__ W1,
                    const float* __restrict__ b1,
                    const float* __restrict__ W2,
                    const float* __restrict__ b2,
                    const float* __restrict__ W3,
                    const float* __restrict__ b3,
                    float* __restrict__ out) {
    __shared__ __align__(16) ull hbuf[4][2][2][32];   // [warp][parity][elem][lane]

    const int w  = threadIdx.x >> 5;     // warp in CTA (0..3) -> SMSP w
    const int l  = threadIdx.x & 31;
    const int jA = l;
    const int jB = l + 32;
    const int u0 = 2 * l;

    const float Kf = 2.8853900817779268f;   // 2*log2(e), folded into pre-activations

    // ---- loop-invariant weights in registers (pre-scaled by Kf) ----
    const ull c1a = pk2(Kf * __ldg(&W1[u0]),      Kf * __ldg(&W1[u0 + 1]));
    const ull c1b = pk2(Kf * __ldg(&W1[64 + u0]), Kf * __ldg(&W1[64 + u0 + 1]));
    const ull cb1 = pk2(Kf * __ldg(&b1[u0]),      Kf * __ldg(&b1[u0 + 1]));

    ull w2A[32], w2B[32];
#pragma unroll
    for (int s = 0; s < 32; ++s) {
        w2A[s] = pk2(Kf * __ldg(&W2[(2 * s) * 64 + jA]),
                     Kf * __ldg(&W2[(2 * s + 1) * 64 + jA]));
        w2B[s] = pk2(Kf * __ldg(&W2[(2 * s) * 64 + jB]),
                     Kf * __ldg(&W2[(2 * s + 1) * 64 + jB]));
    }
    const float b2A = Kf * __ldg(&b2[jA]);
    const float b2B = Kf * __ldg(&b2[jB]);
    const float w3A = __ldg(&W3[jA]);
    const float w3B = __ldg(&W3[jB]);
    const float b3v = __ldg(&b3[0]);

    // this warp's two elements
    const int eg = blockIdx.x * 4 + w;                 // warp-global index, < 1024
    const float2* xp0 = (const float2*)(x + (size_t)(eg * 2) * 2048);
    const float2* xp1 = xp0 + 1024;
    float* op0 = out + (size_t)(eg * 2) * 1024;
    float* op1 = op0 + 1024;

    float gamma0 = 0.0f, gamma1 = 0.0f;
    float2 xv0 = __ldg(&xp0[0]);
    float2 xv1 = __ldg(&xp1[0]);
    const ull zero2 = pk2(0.0f, 0.0f);

#pragma unroll 2
    for (int t = 0; t < 1024; ++t) {
        const int par = t & 1;
        const float eps0 = xv0.x, dtn0 = xv0.y;
        const float eps1 = xv1.x, dtn1 = xv1.y;
        if (t < 1023) { xv0 = __ldg(&xp0[t + 1]); xv1 = __ldg(&xp1[t + 1]); }

        // off-chain: fold dtn*b3 into gamma early (layer1 uses ORIGINAL gamma)
        const float gpre0 = fmaf(dtn0, b3v, gamma0);
        const float gpre1 = fmaf(dtn1, b3v, gamma1);

        // ---- layer 1 (both elements) ----
        {
            const ull p0 = ffma2(dup2(gamma0), c1b, ffma2(dup2(eps0), c1a, cb1));
            const ull p1 = ffma2(dup2(gamma1), c1b, ffma2(dup2(eps1), c1a, cb1));
            const float2 q0 = upk2(p0);
            const float2 q1 = upk2(p1);
            hbuf[w][par][0][l] = pk2(tanh_pre(q0.x), tanh_pre(q0.y));
            hbuf[w][par][1][l] = pk2(tanh_pre(q1.x), tanh_pre(q1.y));
        }
        __syncwarp();

        // ---- layer 2 + 3 partial (both elements, depth-8 chains) ----
        float gp[2];
#pragma unroll
        for (int e = 0; e < 2; ++e) {
            const ulonglong2* hp = (const ulonglong2*)&hbuf[w][par][e][0];
            ull A0 = pk2(b2A, 0.0f), A1 = zero2, A2 = zero2, A3 = zero2;
            ull B0 = pk2(b2B, 0.0f), B1 = zero2, B2 = zero2, B3 = zero2;
#pragma unroll
            for (int k = 0; k < 8; ++k) {
                const ulonglong2 ha = hp[2 * k];
                const ulonglong2 hb = hp[2 * k + 1];
                A0 = ffma2(ha.x, w2A[4 * k],     A0);
                B0 = ffma2(ha.x, w2B[4 * k],     B0);
                A1 = ffma2(ha.y, w2A[4 * k + 1], A1);
                B1 = ffma2(ha.y, w2B[4 * k + 1], B1);
                A2 = ffma2(hb.x, w2A[4 * k + 2], A2);
                B2 = ffma2(hb.x, w2B[4 * k + 2], B2);
                A3 = ffma2(hb.y, w2A[4 * k + 3], A3);
                B3 = ffma2(hb.y, w2B[4 * k + 3], B3);
            }
            const float2 aA = upk2(add2(add2(A0, A1), add2(A2, A3)));
            const float2 aB = upk2(add2(add2(B0, B1), add2(B2, B3)));
            gp[e] = fmaf(tanh_pre(aA.x + aA.y), w3A,
                         tanh_pre(aB.x + aB.y) * w3B);
        }

        // ---- warp-wide sums: interleaved butterflies (latencies overlap) ----
#pragma unroll
        for (int d = 1; d < 32; d <<= 1) {
            const float s0 = __shfl_xor_sync(FULLMASK, gp[0], d);
            const float s1 = __shfl_xor_sync(FULLMASK, gp[1], d);
            gp[0] += s0;
            gp[1] += s1;
        }

        // ---- gamma update + output ----
        gamma0 = fmaf(dtn0, gp[0], gpre0);
        gamma1 = fmaf(dtn1, gp[1], gpre1);

        // sigma = 0.5*eps + 2*(eps - gamma) = 2.5*eps - 2*gamma
        if (l == 0) op0[t] = fmaf(-2.0f, gamma0, 2.5f * eps0);
        if (l == 1) op1[t] = fmaf(-2.0f, gamma1, 2.5f * eps1);
    }
}

extern "C" void kernel_launch(void* const* d_in, const int* in_sizes, int n_in,
                              void* d_out, int out_size) {
    (void)in_sizes; (void)n_in; (void)out_size;
    const float* x  = (const float*)d_in[0];
    const float* W1 = (const float*)d_in[1];
    const float* b1 = (const float*)d_in[2];
    const float* W2 = (const float*)d_in[3];
    const float* b2 = (const float*)d_in[4];
    const float* W3 = (const float*)d_in[5];
    const float* b3 = (const float*)d_in[6];
    float* out = (float*)d_out;

    // 4 independent warps per 128-thread CTA (one per SMSP), 2 elems/warp:
    // 256 CTAs = 1024 warps, single wave, <=2 CTAs/SM.
    maxwell_ffnn_kernel<<<256, 128>>>(x, W1, b1, W2, b2, W3, b3, out);
}

// round 12
// speedup vs baseline: 1.6722x; 1.3103x over previous
#include <cuda_runtime.h>

#define FULLMASK 0xffffffffu
typedef unsigned long long ull;

// ---------- packed f32x2 helpers (Blackwell sm_103a) ----------
__device__ __forceinline__ ull pk2(float a, float b) {
    ull r;
    asm("mov.b64 %0, {%1, %2};" : "=l"(r) : "f"(a), "f"(b));
    return r;
}
__device__ __forceinline__ float2 upk2(ull v) {
    float2 r;
    asm("mov.b64 {%0, %1}, %2;" : "=f"(r.x), "=f"(r.y) : "l"(v));
    return r;
}
__device__ __forceinline__ ull dup2(float a) { return pk2(a, a); }

__device__ __forceinline__ ull ffma2(ull a, ull b, ull c) {
    ull d;
    asm("fma.rn.f32x2 %0, %1, %2, %3;" : "=l"(d) : "l"(a), "l"(b), "l"(c));
    return d;
}
__device__ __forceinline__ ull add2(ull a, ull b) {
    ull d;
    asm("add.rn.f32x2 %0, %1, %2;" : "=l"(d) : "l"(a), "l"(b));
    return d;
}

// HW tanh: single MUFU.TANH (sm_75+), abs err ~1e-5 — 100x inside our budget
__device__ __forceinline__ float tanh_hw(float z) {
    float r;
    asm("tanh.approx.f32 %0, %1;" : "=f"(r) : "f"(z));
    return r;
}

// warp sum via integer redux (s32 form IS supported on sm_103):
// input pre-scaled by 2^23, output = sum * 2^23
__device__ __forceinline__ float redux_scaled(float gp_scaled) {
    int gi, si;
    asm("cvt.rni.s32.f32 %0, %1;" : "=r"(gi) : "f"(gp_scaled));
    asm("redux.sync.add.s32 %0, %1, 0xffffffff;" : "=r"(si) : "r"(gi));
    float sf;
    asm("cvt.rn.f32.s32 %0, %1;" : "=f"(sf) : "r"(si));
    return sf;
}

// Best-known skeleton (R4: 1024 single-warp CTAs, 2 elements/warp) with the
// serial tail attacked: HW tanh (MUFU.TANH) and redux.sync.add.s32 reduction.
// Lane l owns h1 units (2l,2l+1) and layer-2 cols (l, l+32); W2 in 128 regs.
__global__ void __launch_bounds__(32)
maxwell_ffnn_kernel(const float* __restrict__ x,
                    const float* __restrict__ W1,
                    const float* __restrict__ b1,
                    const float* __restrict__ W2,
                    const float* __restrict__ b2,
                    const float* __restrict__ W3,
                    const float* __restrict__ b3,
                    float* __restrict__ out) {
    __shared__ __align__(16) ull hbuf[2][2][32];   // [parity][elem][lane]

    const int l  = threadIdx.x & 31;
    const int jA = l;
    const int jB = l + 32;
    const int u0 = 2 * l;

    const float SC = 8388608.0f;               // 2^23 (redux scale)
    const float IS = 1.1920928955078125e-7f;   // 2^-23

    // ---- loop-invariant weights in registers ----
    const ull c1a = pk2(__ldg(&W1[u0]),      __ldg(&W1[u0 + 1]));
    const ull c1b = pk2(__ldg(&W1[64 + u0]), __ldg(&W1[64 + u0 + 1]));
    const ull cb1 = pk2(__ldg(&b1[u0]),      __ldg(&b1[u0 + 1]));

    ull w2A[32], w2B[32];
#pragma unroll
    for (int s = 0; s < 32; ++s) {
        w2A[s] = pk2(__ldg(&W2[(2 * s) * 64 + jA]),
                     __ldg(&W2[(2 * s + 1) * 64 + jA]));
        w2B[s] = pk2(__ldg(&W2[(2 * s) * 64 + jB]),
                     __ldg(&W2[(2 * s + 1) * 64 + jB]));
    }
    const float b2A = __ldg(&b2[jA]);
    const float b2B = __ldg(&b2[jB]);
    const float w3A = SC * __ldg(&W3[jA]);     // 2^23 * W3 (for integer redux)
    const float w3B = SC * __ldg(&W3[jB]);
    const float b3v = __ldg(&b3[0]);

    const float2* xp0 = (const float2*)(x + (size_t)(blockIdx.x * 2) * 2048);
    const float2* xp1 = xp0 + 1024;
    float* op0 = out + (size_t)(blockIdx.x * 2) * 1024;
    float* op1 = op0 + 1024;

    float gamma0 = 0.0f, gamma1 = 0.0f;
    float2 xv0 = __ldg(&xp0[0]);
    float2 xv1 = __ldg(&xp1[0]);
    const ull zero2 = pk2(0.0f, 0.0f);

#pragma unroll 2
    for (int t = 0; t < 1024; ++t) {
        const int par = t & 1;
        const float eps0 = xv0.x, dtn0 = xv0.y;
        const float eps1 = xv1.x, dtn1 = xv1.y;
        if (t < 1023) { xv0 = __ldg(&xp0[t + 1]); xv1 = __ldg(&xp1[t + 1]); }

        // off-chain: fold dtn*b3 into gamma early (layer1 uses ORIGINAL gamma)
        const float gpre0 = fmaf(dtn0, b3v, gamma0);
        const float gpre1 = fmaf(dtn1, b3v, gamma1);

        // ---- layer 1 (both elements): 2 ffma2 + 2 MUFU.TANH each ----
        {
            const ull p0 = ffma2(dup2(gamma0), c1b, ffma2(dup2(eps0), c1a, cb1));
            const ull p1 = ffma2(dup2(gamma1), c1b, ffma2(dup2(eps1), c1a, cb1));
            const float2 q0 = upk2(p0);
            const float2 q1 = upk2(p1);
            hbuf[par][0][l] = pk2(tanh_hw(q0.x), tanh_hw(q0.y));
            hbuf[par][1][l] = pk2(tanh_hw(q1.x), tanh_hw(q1.y));
        }
        __syncwarp();

        // ---- layer 2 + 3 partial (both elements, depth-8 chains) ----
        float gp[2];
#pragma unroll
        for (int e = 0; e < 2; ++e) {
            const ulonglong2* hp = (const ulonglong2*)&hbuf[par][e][0];
            ull A0 = pk2(b2A, 0.0f), A1 = zero2, A2 = zero2, A3 = zero2;
            ull B0 = pk2(b2B, 0.0f), B1 = zero2, B2 = zero2, B3 = zero2;
#pragma unroll
            for (int k = 0; k < 8; ++k) {
                const ulonglong2 ha = hp[2 * k];
                const ulonglong2 hb = hp[2 * k + 1];
                A0 = ffma2(ha.x, w2A[4 * k],     A0);
                B0 = ffma2(ha.x, w2B[4 * k],     B0);
                A1 = ffma2(ha.y, w2A[4 * k + 1], A1);
                B1 = ffma2(ha.y, w2B[4 * k + 1], B1);
                A2 = ffma2(hb.x, w2A[4 * k + 2], A2);
                B2 = ffma2(hb.x, w2B[4 * k + 2], B2);
                A3 = ffma2(hb.y, w2A[4 * k + 3], A3);
                B3 = ffma2(hb.y, w2B[4 * k + 3], B3);
            }
            const float2 aA = upk2(add2(add2(A0, A1), add2(A2, A3)));
            const float2 aB = upk2(add2(add2(B0, B1), add2(B2, B3)));
            // scaled by 2^23 via w3A/w3B for the integer redux
            gp[e] = fmaf(tanh_hw(aA.x + aA.y), w3A,
                         tanh_hw(aB.x + aB.y) * w3B);
        }

        // ---- warp sums: single-instruction integer redux per element ----
        const float s0 = redux_scaled(gp[0]);
        const float s1 = redux_scaled(gp[1]);

        // ---- gamma update + output ----
        gamma0 = fmaf(dtn0 * IS, s0, gpre0);
        gamma1 = fmaf(dtn1 * IS, s1, gpre1);

        // sigma = 0.5*eps + 2*(eps - gamma) = 2.5*eps - 2*gamma
        if (l == 0) op0[t] = fmaf(-2.0f, gamma0, 2.5f * eps0);
        if (l == 1) op1[t] = fmaf(-2.0f, gamma1, 2.5f * eps1);
    }
}

extern "C" void kernel_launch(void* const* d_in, const int* in_sizes, int n_in,
                              void* d_out, int out_size) {
    (void)in_sizes; (void)n_in; (void)out_size;
    const float* x  = (const float*)d_in[0];
    const float* W1 = (const float*)d_in[1];
    const float* b1 = (const float*)d_in[2];
    const float* W2 = (const float*)d_in[3];
    const float* b2 = (const float*)d_in[4];
    const float* W3 = (const float*)d_in[5];
    const float* b3 = (const float*)d_in[6];
    float* out = (float*)d_out;

    // 2 elements per warp: 1024 single-warp CTAs (~7/SM, single wave)
    maxwell_ffnn_kernel<<<1024, 32>>>(x, W1, b1, W2, b2, W3, b3, out);
}